// round 7
// baseline (speedup 1.0000x reference)
#include <cuda_runtime.h>

// Problem constants (fixed shapes from reference_code)
#define E_    3
#define QE_   60000
#define P_    40
#define H_    20
#define NIMG_ 1800
#define Q_    (E_ * QE_)        // 180000 atoms
#define NNZ_  14400000
#define AB    256               // atoms per block
#define NB    704               // ceil(Q_/AB)

// Scratch (static device globals — sanctioned)
__device__ float g_dE[(size_t)Q_ * P_];        // NEGATED dE/dFP, sorted order, 28.8 MB
__device__ int   g_hist[(size_t)NIMG_ * NB];
__device__ int   g_key_total[NIMG_];
__device__ int   g_key_base[NIMG_];

__device__ __forceinline__ float tanh_fast(float x) {
    float y;
    asm("tanh.approx.f32 %0, %1;" : "=f"(y) : "f"(x));
    return y;
}

// ---------------------------------------------------------------------------
// Histogram of image_idx, fused with zeroing of the output buffer.
// ---------------------------------------------------------------------------
__global__ void k_hist(const int* __restrict__ idx,
                       float* __restrict__ out, int out_n) {
    __shared__ int h[NIMG_];
    for (int k = threadIdx.x; k < NIMG_; k += blockDim.x) h[k] = 0;

    for (int i = blockIdx.x * AB + threadIdx.x; i < out_n; i += NB * AB)
        out[i] = 0.0f;
    __syncthreads();

    int a = blockIdx.x * AB + threadIdx.x;
    if (a < Q_) atomicAdd(&h[idx[a]], 1);
    __syncthreads();
    for (int k = threadIdx.x; k < NIMG_; k += blockDim.x)
        g_hist[(size_t)k * NB + blockIdx.x] = h[k];
}

// ---------------------------------------------------------------------------
// Per-key exclusive scan over blocks: warp-shuffle 2-level scan.
// grid = NIMG_, block = 704 (22 warps, exactly NB lanes).
// ---------------------------------------------------------------------------
__global__ void k_scan_blocks() {
    __shared__ int wsum[22];
    int k = blockIdx.x, t = threadIdx.x;
    int lane = t & 31, w = t >> 5;
    int v = g_hist[(size_t)k * NB + t];
    int s = v;
    #pragma unroll
    for (int o = 1; o < 32; o <<= 1) {
        int x = __shfl_up_sync(0xFFFFFFFFu, s, o);
        if (lane >= o) s += x;
    }
    if (lane == 31) wsum[w] = s;
    __syncthreads();
    if (w == 0) {
        int ws = (lane < 22) ? wsum[lane] : 0;
        #pragma unroll
        for (int o = 1; o < 32; o <<= 1) {
            int x = __shfl_up_sync(0xFFFFFFFFu, ws, o);
            if (lane >= o) ws += x;
        }
        if (lane < 22) wsum[lane] = ws;
    }
    __syncthreads();
    int incl = ((w > 0) ? wsum[w - 1] : 0) + s;
    g_hist[(size_t)k * NB + t] = incl - v;   // exclusive
    if (t == NB - 1) g_key_total[k] = incl;
}

// ---------------------------------------------------------------------------
// Exclusive scan over 1800 key totals (2 elems/thread, shuffle scan).
// ---------------------------------------------------------------------------
__global__ void k_scan_keys() {
    __shared__ int wsum[32];
    int t = threadIdx.x, lane = t & 31, w = t >> 5;
    int i0 = 2 * t, i1 = 2 * t + 1;
    int v0 = (i0 < NIMG_) ? g_key_total[i0] : 0;
    int v1 = (i1 < NIMG_) ? g_key_total[i1] : 0;
    int p = v0 + v1, s = p;
    #pragma unroll
    for (int o = 1; o < 32; o <<= 1) {
        int x = __shfl_up_sync(0xFFFFFFFFu, s, o);
        if (lane >= o) s += x;
    }
    if (lane == 31) wsum[w] = s;
    __syncthreads();
    if (w == 0) {
        int ws = wsum[lane];
        #pragma unroll
        for (int o = 1; o < 32; o <<= 1) {
            int x = __shfl_up_sync(0xFFFFFFFFu, ws, o);
            if (lane >= o) ws += x;
        }
        wsum[lane] = ws;
    }
    __syncthreads();
    int excl = ((w > 0) ? wsum[w - 1] : 0) + s - p;
    if (i0 < NIMG_) g_key_base[i0] = excl;
    if (i1 < NIMG_) g_key_base[i1] = excl + v0;
}

// ---------------------------------------------------------------------------
// Fused: stable rank + MLP fwd + input-grad + energy scatter.
// Register economy: only TWO live 20-float register arrays at any point
// (g1 overwrites h1 in place). __launch_bounds__(256,4) caps regs at 64
// -> 4 CTAs/SM -> ~50% occupancy (was 128 regs / 23.6% occ / 103 us).
// ---------------------------------------------------------------------------
__global__ void __launch_bounds__(AB, 4) k_mlp(
    const float* __restrict__ fps, const float* __restrict__ W1,
    const float* __restrict__ b1,  const float* __restrict__ W2,
    const float* __restrict__ b2,  const float* __restrict__ W3,
    const float* __restrict__ b3,  const int* __restrict__ idx,
    float* __restrict__ energy)
{
    __shared__ float sW1[E_ * P_ * H_];
    __shared__ float sB1[E_ * H_];
    __shared__ float sW2[E_ * H_ * H_];
    __shared__ float sB2[E_ * H_];
    __shared__ float sW3[E_ * H_];
    __shared__ float sB3[E_];
    __shared__ int   skey[AB];

    int t = threadIdx.x;
    for (int i = t; i < E_ * P_ * H_; i += AB) sW1[i] = W1[i];
    for (int i = t; i < E_ * H_;      i += AB) sB1[i] = b1[i];
    for (int i = t; i < E_ * H_ * H_; i += AB) sW2[i] = W2[i];
    for (int i = t; i < E_ * H_;      i += AB) sB2[i] = b2[i];
    for (int i = t; i < E_ * H_;      i += AB) sW3[i] = W3[i];
    if (t < E_) sB3[t] = b3[t];

    int a = blockIdx.x * AB + t;
    int key = (a < Q_) ? idx[a] : -1;
    skey[t] = key;
    __syncthreads();
    if (a >= Q_) return;

    // stable local rank: # of earlier same-key atoms in this block
    // (broadcast LDS reads: all lanes read the same skey[j] per iteration)
    int lr = 0;
    {
        int j = 0;
        #pragma unroll 4
        for (; j + 4 <= t; j += 4) {
            lr += (skey[j]     == key);
            lr += (skey[j + 1] == key);
            lr += (skey[j + 2] == key);
            lr += (skey[j + 3] == key);
        }
        for (; j < t; j++) lr += (skey[j] == key);
    }
    int pos = g_key_base[key] + g_hist[(size_t)key * NB + blockIdx.x] + lr;

    int e = a / QE_;
    const float* w1 = sW1 + e * P_ * H_;
    const float* w2 = sW2 + e * H_ * H_;
    const float* w3 = sW3 + e * H_;

    float h1[H_];
    #pragma unroll
    for (int h = 0; h < H_; h++) h1[h] = sB1[e * H_ + h];

    // layer 1: stream x as float4
    const float4* xrow = (const float4*)(fps + (size_t)a * P_);
    #pragma unroll 2
    for (int p4 = 0; p4 < P_ / 4; p4++) {
        float4 x = xrow[p4];
        const float* w1p = w1 + p4 * 4 * H_;
        #pragma unroll
        for (int h = 0; h < H_; h++) {
            float s = fmaf(x.x, w1p[h], h1[h]);
            s = fmaf(x.y, w1p[H_ + h], s);
            s = fmaf(x.z, w1p[2 * H_ + h], s);
            h1[h] = fmaf(x.w, w1p[3 * H_ + h], s);
        }
    }
    #pragma unroll
    for (int h = 0; h < H_; h++) h1[h] = tanh_fast(h1[h]);

    // layer 2 (g2 seeds backward in place afterwards)
    float g2[H_];
    #pragma unroll
    for (int j = 0; j < H_; j++) {
        float s = sB2[e * H_ + j];
        #pragma unroll
        for (int h = 0; h < H_; h++) s = fmaf(h1[h], w2[h * H_ + j], s);
        g2[j] = tanh_fast(s);
    }

    // layer 3 fwd + backward seed: g2[j] <- w3[j]*(1-h2[j]^2)
    float en = sB3[e];
    #pragma unroll
    for (int j = 0; j < H_; j++) {
        float v = g2[j];
        en = fmaf(v, w3[j], en);
        g2[j] = w3[j] * (1.0f - v * v);
    }
    atomicAdd(&energy[key], en);

    // g1 overwrites h1 IN PLACE: g1[h] = (W2[h,:]@g2) * (1-h1[h]^2)
    #pragma unroll
    for (int h = 0; h < H_; h++) {
        float s = 0.0f;
        #pragma unroll
        for (int j = 0; j < H_; j++) s = fmaf(w2[h * H_ + j], g2[j], s);
        h1[h] = s * (1.0f - h1[h] * h1[h]);
    }

    // -dE/dx = -(W1 @ g1), float4 stores into sorted position
    float4* dst = (float4*)(g_dE + (size_t)pos * P_);
    #pragma unroll 2
    for (int p4 = 0; p4 < P_ / 4; p4++) {
        const float* w1p = w1 + p4 * 4 * H_;
        float4 o;
        float s0 = 0, s1 = 0, s2 = 0, s3 = 0;
        #pragma unroll
        for (int h = 0; h < H_; h++) {
            s0 = fmaf(w1p[h],          h1[h], s0);
            s1 = fmaf(w1p[H_ + h],     h1[h], s1);
            s2 = fmaf(w1p[2 * H_ + h], h1[h], s2);
            s3 = fmaf(w1p[3 * H_ + h], h1[h], s3);
        }
        o.x = -s0; o.y = -s1; o.z = -s2; o.w = -s3;
        dst[p4] = o;
    }
}

// ---------------------------------------------------------------------------
// Sparse COO transpose-matvec (best-known form): one int4-group/thread,
// __ldcs streaming on COO arrays so g_dE + force stay L2-resident.
// ---------------------------------------------------------------------------
__global__ void k_scatter(const int4* __restrict__ rows,
                          const int4* __restrict__ cols,
                          const float4* __restrict__ vals,
                          float* __restrict__ force)
{
    int i = blockIdx.x * blockDim.x + threadIdx.x;
    if (i >= NNZ_ / 4) return;
    int4   r = __ldcs(&rows[i]);
    int4   c = __ldcs(&cols[i]);
    float4 v = __ldcs(&vals[i]);
    float d0 = __ldg(&g_dE[r.x]);
    float d1 = __ldg(&g_dE[r.y]);
    float d2 = __ldg(&g_dE[r.z]);
    float d3 = __ldg(&g_dE[r.w]);
    atomicAdd(&force[c.x], v.x * d0);
    atomicAdd(&force[c.y], v.y * d1);
    atomicAdd(&force[c.z], v.z * d2);
    atomicAdd(&force[c.w], v.w * d3);
}

// ---------------------------------------------------------------------------
extern "C" void kernel_launch(void* const* d_in, const int* in_sizes, int n_in,
                              void* d_out, int out_size)
{
    const float* fps       = (const float*)d_in[0];
    const float* W1        = (const float*)d_in[1];
    const float* b1        = (const float*)d_in[2];
    const float* W2        = (const float*)d_in[3];
    const float* b2        = (const float*)d_in[4];
    const float* W3        = (const float*)d_in[5];
    const float* b3        = (const float*)d_in[6];
    const int*   image_idx = (const int*)d_in[7];
    const int*   fp_rows   = (const int*)d_in[8];
    const int*   fp_cols   = (const int*)d_in[9];
    const float* fp_vals   = (const float*)d_in[10];

    float* out    = (float*)d_out;
    float* energy = out;               // [NIMG, 1]
    float* force  = out + NIMG_;       // [Q, 3] flattened

    k_hist<<<NB, AB>>>(image_idx, out, out_size);
    k_scan_blocks<<<NIMG_, NB>>>();
    k_scan_keys<<<1, 1024>>>();

    k_mlp<<<NB, AB>>>(fps, W1, b1, W2, b2, W3, b3, image_idx, energy);

    k_scatter<<<(NNZ_ / 4 + 255) / 256, 256>>>(
        (const int4*)fp_rows, (const int4*)fp_cols, (const float4*)fp_vals, force);
}

// round 8
// speedup vs baseline: 1.6342x; 1.6342x over previous
#include <cuda_runtime.h>

// Problem constants (fixed shapes from reference_code)
#define E_    3
#define QE_   60000
#define P_    40
#define H_    20
#define NIMG_ 1800
#define Q_    (E_ * QE_)        // 180000 atoms
#define NNZ_  14400000
#define AB    256               // atoms per block
#define NB    704               // ceil(Q_/AB)

// Scratch (static device globals — sanctioned)
__device__ float g_dE[(size_t)Q_ * P_];        // NEGATED dE/dFP, sorted order, 28.8 MB
__device__ int   g_hist[(size_t)NIMG_ * NB];
__device__ int   g_key_total[NIMG_];
__device__ int   g_key_base[NIMG_];

__device__ __forceinline__ float tanh_fast(float x) {
    float y;
    asm("tanh.approx.f32 %0, %1;" : "=f"(y) : "f"(x));
    return y;
}

// ---------------------------------------------------------------------------
// Histogram of image_idx, fused with zeroing of the output buffer.
// ---------------------------------------------------------------------------
__global__ void k_hist(const int* __restrict__ idx,
                       float* __restrict__ out, int out_n) {
    __shared__ int h[NIMG_];
    for (int k = threadIdx.x; k < NIMG_; k += blockDim.x) h[k] = 0;

    for (int i = blockIdx.x * AB + threadIdx.x; i < out_n; i += NB * AB)
        out[i] = 0.0f;
    __syncthreads();

    int a = blockIdx.x * AB + threadIdx.x;
    if (a < Q_) atomicAdd(&h[idx[a]], 1);
    __syncthreads();
    for (int k = threadIdx.x; k < NIMG_; k += blockDim.x)
        g_hist[(size_t)k * NB + blockIdx.x] = h[k];
}

// ---------------------------------------------------------------------------
// Per-key exclusive scan over blocks: warp-shuffle 2-level scan.
// ---------------------------------------------------------------------------
__global__ void k_scan_blocks() {
    __shared__ int wsum[22];
    int k = blockIdx.x, t = threadIdx.x;
    int lane = t & 31, w = t >> 5;
    int v = g_hist[(size_t)k * NB + t];
    int s = v;
    #pragma unroll
    for (int o = 1; o < 32; o <<= 1) {
        int x = __shfl_up_sync(0xFFFFFFFFu, s, o);
        if (lane >= o) s += x;
    }
    if (lane == 31) wsum[w] = s;
    __syncthreads();
    if (w == 0) {
        int ws = (lane < 22) ? wsum[lane] : 0;
        #pragma unroll
        for (int o = 1; o < 32; o <<= 1) {
            int x = __shfl_up_sync(0xFFFFFFFFu, ws, o);
            if (lane >= o) ws += x;
        }
        if (lane < 22) wsum[lane] = ws;
    }
    __syncthreads();
    int incl = ((w > 0) ? wsum[w - 1] : 0) + s;
    g_hist[(size_t)k * NB + t] = incl - v;   // exclusive
    if (t == NB - 1) g_key_total[k] = incl;
}

// ---------------------------------------------------------------------------
// Exclusive scan over 1800 key totals (2 elems/thread, shuffle scan).
// ---------------------------------------------------------------------------
__global__ void k_scan_keys() {
    __shared__ int wsum[32];
    int t = threadIdx.x, lane = t & 31, w = t >> 5;
    int i0 = 2 * t, i1 = 2 * t + 1;
    int v0 = (i0 < NIMG_) ? g_key_total[i0] : 0;
    int v1 = (i1 < NIMG_) ? g_key_total[i1] : 0;
    int p = v0 + v1, s = p;
    #pragma unroll
    for (int o = 1; o < 32; o <<= 1) {
        int x = __shfl_up_sync(0xFFFFFFFFu, s, o);
        if (lane >= o) s += x;
    }
    if (lane == 31) wsum[w] = s;
    __syncthreads();
    if (w == 0) {
        int ws = wsum[lane];
        #pragma unroll
        for (int o = 1; o < 32; o <<= 1) {
            int x = __shfl_up_sync(0xFFFFFFFFu, ws, o);
            if (lane >= o) ws += x;
        }
        wsum[lane] = ws;
    }
    __syncthreads();
    int excl = ((w > 0) ? wsum[w - 1] : 0) + s - p;
    if (i0 < NIMG_) g_key_base[i0] = excl;
    if (i1 < NIMG_) g_key_base[i1] = excl + v0;
}

// ---------------------------------------------------------------------------
// Fused: stable rank + MLP fwd + input-grad + energy scatter.
// Dual-layout weights in smem: each GEMV loop reads its weight matrix along
// the CONTIGUOUS axis via LDS.128 (float4) — ~600 vector LDS/thread instead
// of ~2400 scalar LDS. launch_bounds(256,3) targets 80 regs -> 3 CTAs/SM.
// ---------------------------------------------------------------------------
__global__ void __launch_bounds__(AB, 3) k_mlp(
    const float* __restrict__ fps, const float* __restrict__ W1,
    const float* __restrict__ b1,  const float* __restrict__ W2,
    const float* __restrict__ b2,  const float* __restrict__ W3,
    const float* __restrict__ b3,  const int* __restrict__ idx,
    float* __restrict__ energy)
{
    __shared__ __align__(16) float sW1 [E_ * P_ * H_];   // [P][H] per element
    __shared__ __align__(16) float sW1T[E_ * P_ * H_];   // [H][P] per element
    __shared__ __align__(16) float sW2 [E_ * H_ * H_];   // [H][H]
    __shared__ __align__(16) float sW2T[E_ * H_ * H_];   // [H][H] transposed
    __shared__ float sB1[E_ * H_];
    __shared__ float sB2[E_ * H_];
    __shared__ float sW3[E_ * H_];
    __shared__ float sB3[E_];
    __shared__ int   skey[AB];

    int t = threadIdx.x;
    for (int i = t; i < E_ * P_ * H_; i += AB) {
        float v = W1[i];
        sW1[i] = v;
        int e = i / (P_ * H_), r = i % (P_ * H_);
        int p = r / H_, h = r % H_;
        sW1T[e * P_ * H_ + h * P_ + p] = v;
    }
    for (int i = t; i < E_ * H_ * H_; i += AB) {
        float v = W2[i];
        sW2[i] = v;
        int e = i / (H_ * H_), r = i % (H_ * H_);
        int hh = r / H_, j = r % H_;
        sW2T[e * H_ * H_ + j * H_ + hh] = v;
    }
    for (int i = t; i < E_ * H_; i += AB) {
        sB1[i] = b1[i];
        sB2[i] = b2[i];
        sW3[i] = W3[i];
    }
    if (t < E_) sB3[t] = b3[t];

    int a = blockIdx.x * AB + t;
    int key = (a < Q_) ? idx[a] : -1;
    skey[t] = key;
    __syncthreads();
    if (a >= Q_) return;

    // stable local rank: # of earlier same-key atoms in this block
    int lr = 0;
    {
        int j = 0;
        #pragma unroll 4
        for (; j + 4 <= t; j += 4) {
            lr += (skey[j]     == key);
            lr += (skey[j + 1] == key);
            lr += (skey[j + 2] == key);
            lr += (skey[j + 3] == key);
        }
        for (; j < t; j++) lr += (skey[j] == key);
    }
    int pos = g_key_base[key] + g_hist[(size_t)key * NB + blockIdx.x] + lr;

    int e = a / QE_;
    const float*  w1  = sW1  + e * P_ * H_;   // [P][H]
    const float*  w1t = sW1T + e * P_ * H_;   // [H][P]
    const float*  w2  = sW2  + e * H_ * H_;   // [h][j]
    const float*  w2t = sW2T + e * H_ * H_;   // [j][h]
    const float*  w3  = sW3  + e * H_;

    float h1[H_];
    #pragma unroll
    for (int h = 0; h < H_; h++) h1[h] = sB1[e * H_ + h];

    // layer 1: h1[h] += sum_p x[p]*W1[p][h]  — read W1T[h][p] as float4
    const float4* xrow = (const float4*)(fps + (size_t)a * P_);
    #pragma unroll 2
    for (int p4 = 0; p4 < P_ / 4; p4++) {
        float4 x = xrow[p4];
        #pragma unroll
        for (int h = 0; h < H_; h++) {
            float4 w = *(const float4*)(w1t + h * P_ + p4 * 4);
            float s = fmaf(x.x, w.x, h1[h]);
            s = fmaf(x.y, w.y, s);
            s = fmaf(x.z, w.z, s);
            h1[h] = fmaf(x.w, w.w, s);
        }
    }
    #pragma unroll
    for (int h = 0; h < H_; h++) h1[h] = tanh_fast(h1[h]);

    // layer 2: h2[j] = sum_h h1[h]*W2[h][j] — read W2T[j][h] as float4
    float g2[H_];
    #pragma unroll
    for (int j = 0; j < H_; j++) {
        float s = sB2[e * H_ + j];
        #pragma unroll
        for (int h4 = 0; h4 < H_ / 4; h4++) {
            float4 w = *(const float4*)(w2t + j * H_ + h4 * 4);
            s = fmaf(h1[h4 * 4],     w.x, s);
            s = fmaf(h1[h4 * 4 + 1], w.y, s);
            s = fmaf(h1[h4 * 4 + 2], w.z, s);
            s = fmaf(h1[h4 * 4 + 3], w.w, s);
        }
        g2[j] = tanh_fast(s);
    }

    // layer 3 fwd + backward seed: g2[j] <- w3[j]*(1-h2[j]^2)
    float en = sB3[e];
    #pragma unroll
    for (int j = 0; j < H_; j++) {
        float v = g2[j];
        en = fmaf(v, w3[j], en);
        g2[j] = w3[j] * (1.0f - v * v);
    }
    atomicAdd(&energy[key], en);

    // g1 overwrites h1 IN PLACE: g1[h] = (sum_j W2[h][j]*g2[j]) * (1-h1[h]^2)
    // W2[h][:] contiguous -> float4
    #pragma unroll
    for (int h = 0; h < H_; h++) {
        float s = 0.0f;
        #pragma unroll
        for (int j4 = 0; j4 < H_ / 4; j4++) {
            float4 w = *(const float4*)(w2 + h * H_ + j4 * 4);
            s = fmaf(w.x, g2[j4 * 4],     s);
            s = fmaf(w.y, g2[j4 * 4 + 1], s);
            s = fmaf(w.z, g2[j4 * 4 + 2], s);
            s = fmaf(w.w, g2[j4 * 4 + 3], s);
        }
        h1[h] = s * (1.0f - h1[h] * h1[h]);
    }

    // -dE/dx[p] = -sum_h W1[p][h]*g1[h] — W1[p][:] contiguous -> float4
    float4* dst = (float4*)(g_dE + (size_t)pos * P_);
    #pragma unroll 2
    for (int p4 = 0; p4 < P_ / 4; p4++) {
        float4 o;
        #pragma unroll
        for (int pp = 0; pp < 4; pp++) {
            const float* w1p = w1 + (p4 * 4 + pp) * H_;
            float s = 0.0f;
            #pragma unroll
            for (int h4 = 0; h4 < H_ / 4; h4++) {
                float4 w = *(const float4*)(w1p + h4 * 4);
                s = fmaf(w.x, h1[h4 * 4],     s);
                s = fmaf(w.y, h1[h4 * 4 + 1], s);
                s = fmaf(w.z, h1[h4 * 4 + 2], s);
                s = fmaf(w.w, h1[h4 * 4 + 3], s);
            }
            ((float*)&o)[pp] = -s;
        }
        dst[p4] = o;
    }
}

// ---------------------------------------------------------------------------
// Sparse COO transpose-matvec (best-known form): one int4-group/thread,
// __ldcs streaming on COO arrays so g_dE + force stay L2-resident.
// ---------------------------------------------------------------------------
__global__ void k_scatter(const int4* __restrict__ rows,
                          const int4* __restrict__ cols,
                          const float4* __restrict__ vals,
                          float* __restrict__ force)
{
    int i = blockIdx.x * blockDim.x + threadIdx.x;
    if (i >= NNZ_ / 4) return;
    int4   r = __ldcs(&rows[i]);
    int4   c = __ldcs(&cols[i]);
    float4 v = __ldcs(&vals[i]);
    float d0 = __ldg(&g_dE[r.x]);
    float d1 = __ldg(&g_dE[r.y]);
    float d2 = __ldg(&g_dE[r.z]);
    float d3 = __ldg(&g_dE[r.w]);
    atomicAdd(&force[c.x], v.x * d0);
    atomicAdd(&force[c.y], v.y * d1);
    atomicAdd(&force[c.z], v.z * d2);
    atomicAdd(&force[c.w], v.w * d3);
}

// ---------------------------------------------------------------------------
extern "C" void kernel_launch(void* const* d_in, const int* in_sizes, int n_in,
                              void* d_out, int out_size)
{
    const float* fps       = (const float*)d_in[0];
    const float* W1        = (const float*)d_in[1];
    const float* b1        = (const float*)d_in[2];
    const float* W2        = (const float*)d_in[3];
    const float* b2        = (const float*)d_in[4];
    const float* W3        = (const float*)d_in[5];
    const float* b3        = (const float*)d_in[6];
    const int*   image_idx = (const int*)d_in[7];
    const int*   fp_rows   = (const int*)d_in[8];
    const int*   fp_cols   = (const int*)d_in[9];
    const float* fp_vals   = (const float*)d_in[10];

    float* out    = (float*)d_out;
    float* energy = out;               // [NIMG, 1]
    float* force  = out + NIMG_;       // [Q, 3] flattened

    k_hist<<<NB, AB>>>(image_idx, out, out_size);
    k_scan_blocks<<<NIMG_, NB>>>();
    k_scan_keys<<<1, 1024>>>();

    k_mlp<<<NB, AB>>>(fps, W1, b1, W2, b2, W3, b3, image_idx, energy);

    k_scatter<<<(NNZ_ / 4 + 255) / 256, 256>>>(
        (const int4*)fp_rows, (const int4*)fp_cols, (const float4*)fp_vals, force);
}